// round 1
// baseline (speedup 1.0000x reference)
#include <cuda_runtime.h>
#include <math.h>

// CoarseSNN: 3-layer spiking CNN, T=200 steps, B=8, H=W=128.
// One persistent kernel. 256 independent CTAs, each owns a 16x32 interior tile
// and redundantly maintains halo LIF state in SMEM so no inter-CTA sync or
// state traffic is ever needed. Spikes live as bitmasks (ballot); conv2/conv3
// iterate set bits only (cost ~ spike rate, not dense FLOPs).

#define T_STEPS  200
#define NTHREADS 512
#define NWARPS   16

#define IH 16            // interior rows per CTA
#define IW 32            // interior cols per CTA
#define R2H 18           // layer-2 region (interior + 1 halo)
#define R2W 34
#define R1H 20           // layer-1 region (interior + 2 halo)
#define R1W 36
#define XH 22            // x staging region (interior + 3 halo)
#define XW 38

#define N1 (R1H*R1W)     // 720
#define N2 (R2H*R2W)     // 612
#define N3 (IH*IW)       // 512

struct SmemLayout {
    float xs[XH*XW];         // staged input tile           3344 B
    float v1[N1*16];         // layer-1 membrane           46080 B
    float v2[N2*32];         // layer-2 membrane           78336 B
    float v3[3*N3];          // layer-3 membrane            6144 B
    float accv[3*N3];        // spike accumulator           6144 B
    float w2s[144*32];       // w2 [pos*16+i][o]           18432 B
    float w3s[288*3];        // w3 [pos*32+i][o]            3456 B
    unsigned s1m[N1];        // 16-bit spike masks          2880 B
    unsigned s2m[N2];        // 32-bit spike masks          2448 B
};                           // total ~167264 B

__global__ void __launch_bounds__(NTHREADS, 1)
snn_kernel(const float* __restrict__ xg,  const float* __restrict__ w1g,
           const float* __restrict__ b1g, const float* __restrict__ w2g,
           const float* __restrict__ b2g, const float* __restrict__ w3g,
           const float* __restrict__ b3g, float* __restrict__ outg)
{
    extern __shared__ unsigned char smem_raw[];
    SmemLayout* sm = reinterpret_cast<SmemLayout*>(smem_raw);

    const int tid  = threadIdx.x;
    const int lane = tid & 31;
    const int warp = tid >> 5;

    const int bid  = blockIdx.x;
    const int img  = bid >> 5;          // 8 images
    const int tile = bid & 31;          // 32 tiles per image (8 row x 4 col)
    const int y0   = (tile >> 2) * IH;
    const int x0   = (tile & 3)  * IW;

    // ---- init state ----
    for (int i = tid; i < N1*16; i += NTHREADS) sm->v1[i] = 0.f;
    for (int i = tid; i < N2*32; i += NTHREADS) sm->v2[i] = 0.f;
    for (int i = tid; i < 3*N3;  i += NTHREADS) { sm->v3[i] = 0.f; sm->accv[i] = 0.f; }

    // ---- stage weights: w2s[(pos*16+i)*32 + o], w3s[(pos*32+i)*3 + o] ----
    for (int j = tid; j < 144*32; j += NTHREADS) {
        int idx = j >> 5, o = j & 31;
        int ic = idx & 15, pos = idx >> 4;
        sm->w2s[j] = w2g[(o*16 + ic)*9 + pos];
    }
    for (int j = tid; j < 288*3; j += NTHREADS) {
        int idx = j / 3, o = j - idx*3;
        int pos = idx >> 5, ic = idx & 31;
        sm->w3s[j] = w3g[(o*32 + ic)*9 + pos];
    }

    // ---- per-lane weight registers ----
    const int c1 = lane & 15;            // layer-1 channel for this lane
    float w1r[9];
    #pragma unroll
    for (int k = 0; k < 9; k++) w1r[k] = w1g[c1*9 + k];
    const float b1r = b1g[c1];
    const float b2r = b2g[lane];         // layer-2 out channel == lane
    const float b30 = b3g[0], b31 = b3g[1], b32 = b3g[2];

    __syncthreads();

    const float* ximg = xg + (size_t)img * (T_STEPS*128*128);

    for (int t = 0; t < T_STEPS; t++) {
        // ---- stage x tile (zero-padded SAME) ----
        const float* xt = ximg + (size_t)t * (128*128);
        for (int i = tid; i < XH*XW; i += NTHREADS) {
            int ry = i / XW, rx = i - ry*XW;
            int gy = y0 + ry - 3, gx = x0 + rx - 3;
            float v = 0.f;
            if ((unsigned)gy < 128u && (unsigned)gx < 128u) v = __ldg(&xt[gy*128 + gx]);
            sm->xs[i] = v;
        }
        __syncthreads();

        // ---- layer 1: half-warp = 16 channels of one pixel ----
        {
            const int half = lane >> 4;
            for (int base = warp; base < N1/2; base += NWARPS) {
                const int p  = base*2 + half;
                const int ry = p / R1W, rx = p - ry*R1W;
                float a = b1r;
                #pragma unroll
                for (int k = 0; k < 9; k++)
                    a = fmaf(w1r[k], sm->xs[(ry + k/3)*XW + (rx + k - (k/3)*3)], a);
                float v = (sm->v1[p*16 + c1] + a) * 0.5f;   // v += (x-v)/2
                const int gy = y0 + ry - 2, gx = x0 + rx - 2;
                const bool sp = (v >= 1.0f) && ((unsigned)gy < 128u) && ((unsigned)gx < 128u);
                sm->v1[p*16 + c1] = sp ? 0.f : v;           // hard reset
                unsigned bal = __ballot_sync(0xffffffffu, sp);
                if (c1 == 0) sm->s1m[p] = (bal >> (half << 4)) & 0xffffu;
            }
        }
        __syncthreads();

        // ---- layer 2: warp = 32 out channels of one pixel; 2 pixels for ILP ----
        for (int pair = warp; pair < N2/2; pair += NWARPS) {
            const int pA = pair*2, pB = pA + 1;
            const int ryA = pA / R2W, rxA = pA - ryA*R2W;
            const int ryB = pB / R2W, rxB = pB - ryB*R2W;

            unsigned mA[9], mB[9];
            #pragma unroll
            for (int ky = 0; ky < 3; ky++)
                #pragma unroll
                for (int kx = 0; kx < 3; kx++) {
                    mA[ky*3+kx] = sm->s1m[(ryA+ky)*R1W + rxA+kx];
                    mB[ky*3+kx] = sm->s1m[(ryB+ky)*R1W + rxB+kx];
                }
            unsigned long long a0 = (unsigned long long)mA[0] | ((unsigned long long)mA[1]<<16)
                                  | ((unsigned long long)mA[2]<<32) | ((unsigned long long)mA[3]<<48);
            unsigned long long a1 = (unsigned long long)mA[4] | ((unsigned long long)mA[5]<<16)
                                  | ((unsigned long long)mA[6]<<32) | ((unsigned long long)mA[7]<<48);
            unsigned long long a2 = (unsigned long long)mA[8];
            unsigned long long e0 = (unsigned long long)mB[0] | ((unsigned long long)mB[1]<<16)
                                  | ((unsigned long long)mB[2]<<32) | ((unsigned long long)mB[3]<<48);
            unsigned long long e1 = (unsigned long long)mB[4] | ((unsigned long long)mB[5]<<16)
                                  | ((unsigned long long)mB[6]<<32) | ((unsigned long long)mB[7]<<48);
            unsigned long long e2 = (unsigned long long)mB[8];

            float accA = b2r, accB = b2r;
            while (a0 | e0) {
                if (a0) { int b = __ffsll((long long)a0) - 1; a0 &= a0 - 1; accA += sm->w2s[(b<<5) + lane]; }
                if (e0) { int b = __ffsll((long long)e0) - 1; e0 &= e0 - 1; accB += sm->w2s[(b<<5) + lane]; }
            }
            while (a1 | e1) {
                if (a1) { int b = __ffsll((long long)a1) - 1; a1 &= a1 - 1; accA += sm->w2s[((64+b)<<5) + lane]; }
                if (e1) { int b = __ffsll((long long)e1) - 1; e1 &= e1 - 1; accB += sm->w2s[((64+b)<<5) + lane]; }
            }
            while (a2 | e2) {
                if (a2) { int b = __ffsll((long long)a2) - 1; a2 &= a2 - 1; accA += sm->w2s[((128+b)<<5) + lane]; }
                if (e2) { int b = __ffsll((long long)e2) - 1; e2 &= e2 - 1; accB += sm->w2s[((128+b)<<5) + lane]; }
            }

            {   // LIF pixel A
                float vA = (sm->v2[pA*32 + lane] + accA) * 0.5f;
                const int gy = y0 + ryA - 1, gx = x0 + rxA - 1;
                const bool sp = (vA >= 1.0f) && ((unsigned)gy < 128u) && ((unsigned)gx < 128u);
                sm->v2[pA*32 + lane] = sp ? 0.f : vA;
                unsigned bal = __ballot_sync(0xffffffffu, sp);
                if (lane == 0) sm->s2m[pA] = bal;
            }
            {   // LIF pixel B
                float vB = (sm->v2[pB*32 + lane] + accB) * 0.5f;
                const int gy = y0 + ryB - 1, gx = x0 + rxB - 1;
                const bool sp = (vB >= 1.0f) && ((unsigned)gy < 128u) && ((unsigned)gx < 128u);
                sm->v2[pB*32 + lane] = sp ? 0.f : vB;
                unsigned bal = __ballot_sync(0xffffffffu, sp);
                if (lane == 0) sm->s2m[pB] = bal;
            }
        }
        __syncthreads();

        // ---- layer 3: thread-per-pixel (N3 == NTHREADS) ----
        {
            const int p  = tid;
            const int ry = p >> 5, rx = p & 31;
            unsigned m[9];
            #pragma unroll
            for (int ky = 0; ky < 3; ky++)
                #pragma unroll
                for (int kx = 0; kx < 3; kx++)
                    m[ky*3+kx] = sm->s2m[(ry+ky)*R2W + rx+kx];
            unsigned long long wds[5];
            wds[0] = (unsigned long long)m[0] | ((unsigned long long)m[1] << 32);
            wds[1] = (unsigned long long)m[2] | ((unsigned long long)m[3] << 32);
            wds[2] = (unsigned long long)m[4] | ((unsigned long long)m[5] << 32);
            wds[3] = (unsigned long long)m[6] | ((unsigned long long)m[7] << 32);
            wds[4] = (unsigned long long)m[8];
            float A0 = b30, A1 = b31, A2 = b32;
            #pragma unroll
            for (int wdi = 0; wdi < 5; wdi++) {
                unsigned long long mm = wds[wdi];
                while (mm) {
                    int b = __ffsll((long long)mm) - 1; mm &= mm - 1;
                    const float* wp = &sm->w3s[(wdi*64 + b)*3];
                    A0 += wp[0]; A1 += wp[1]; A2 += wp[2];
                }
            }
            float av[3] = {A0, A1, A2};
            #pragma unroll
            for (int k = 0; k < 3; k++) {
                float v = (sm->v3[k*N3 + p] + av[k]) * 0.5f;
                bool sp = v >= 1.0f;
                sm->v3[k*N3 + p] = sp ? 0.f : v;
                if (sp) sm->accv[k*N3 + p] += 1.0f;
            }
        }
        __syncthreads();
    }

    // ---- output: sigmoid(acc / T) ----
    {
        const int p  = tid;
        const int gy = y0 + (p >> 5), gx = x0 + (p & 31);
        #pragma unroll
        for (int k = 0; k < 3; k++) {
            float a = sm->accv[k*N3 + p] * (1.0f / T_STEPS);
            outg[((size_t)(img*3 + k)*128 + gy)*128 + gx] = 1.0f / (1.0f + expf(-a));
        }
    }
}

extern "C" void kernel_launch(void* const* d_in, const int* in_sizes, int n_in,
                              void* d_out, int out_size)
{
    (void)in_sizes; (void)n_in; (void)out_size;
    const float* x  = (const float*)d_in[0];
    const float* w1 = (const float*)d_in[1];
    const float* b1 = (const float*)d_in[2];
    const float* w2 = (const float*)d_in[3];
    const float* b2 = (const float*)d_in[4];
    const float* w3 = (const float*)d_in[5];
    const float* b3 = (const float*)d_in[6];
    float* out = (float*)d_out;

    cudaFuncSetAttribute(snn_kernel, cudaFuncAttributeMaxDynamicSharedMemorySize,
                         (int)sizeof(SmemLayout));
    snn_kernel<<<256, NTHREADS, sizeof(SmemLayout)>>>(x, w1, b1, w2, b2, w3, b3, out);
}

// round 2
// speedup vs baseline: 1.0210x; 1.0210x over previous
#include <cuda_runtime.h>
#include <math.h>

// CoarseSNN: 3-layer spiking CNN, T=200 steps, B=8, H=W=128.
// One persistent kernel. 256 independent CTAs, each owns a 16x32 interior tile
// and redundantly maintains halo LIF state in SMEM (no inter-CTA sync ever).
// Spikes are bitmasks (ballot); conv2/conv3 iterate set bits only.
// R2 change: 1024 threads/CTA (32 warps, occ 50%) to hide LDS/FADD chain
// latency; layer 3 split 2 threads/pixel to cut divergent loop length.

#define T_STEPS  200
#define NTHREADS 1024
#define NWARPS   32

#define IH 16            // interior rows per CTA
#define IW 32            // interior cols per CTA
#define R2H 18           // layer-2 region (interior + 1 halo)
#define R2W 34
#define R1H 20           // layer-1 region (interior + 2 halo)
#define R1W 36
#define XH 22            // x staging region (interior + 3 halo)
#define XW 38

#define N1 (R1H*R1W)     // 720
#define N2 (R2H*R2W)     // 612
#define N3 (IH*IW)       // 512

struct SmemLayout {
    float xs[XH*XW];         // staged input tile           3344 B
    float v1[N1*16];         // layer-1 membrane           46080 B
    float v2[N2*32];         // layer-2 membrane           78336 B
    float v3[3*N3];          // layer-3 membrane            6144 B
    float accv[3*N3];        // spike accumulator           6144 B
    float w2s[144*32];       // w2 [pos*16+i][o]           18432 B
    float w3s[288*3];        // w3 [pos*32+i][o]            3456 B
    unsigned s1m[N1];        // 16-bit spike masks          2880 B
    unsigned s2m[N2];        // 32-bit spike masks          2448 B
};                           // total ~167264 B

__global__ void __launch_bounds__(NTHREADS, 1)
snn_kernel(const float* __restrict__ xg,  const float* __restrict__ w1g,
           const float* __restrict__ b1g, const float* __restrict__ w2g,
           const float* __restrict__ b2g, const float* __restrict__ w3g,
           const float* __restrict__ b3g, float* __restrict__ outg)
{
    extern __shared__ unsigned char smem_raw[];
    SmemLayout* sm = reinterpret_cast<SmemLayout*>(smem_raw);

    const int tid  = threadIdx.x;
    const int lane = tid & 31;
    const int warp = tid >> 5;

    const int bid  = blockIdx.x;
    const int img  = bid >> 5;          // 8 images
    const int tile = bid & 31;          // 32 tiles per image (8 row x 4 col)
    const int y0   = (tile >> 2) * IH;
    const int x0   = (tile & 3)  * IW;

    // ---- init state ----
    for (int i = tid; i < N1*16; i += NTHREADS) sm->v1[i] = 0.f;
    for (int i = tid; i < N2*32; i += NTHREADS) sm->v2[i] = 0.f;
    for (int i = tid; i < 3*N3;  i += NTHREADS) { sm->v3[i] = 0.f; sm->accv[i] = 0.f; }

    // ---- stage weights: w2s[(pos*16+i)*32 + o], w3s[(pos*32+i)*3 + o] ----
    for (int j = tid; j < 144*32; j += NTHREADS) {
        int idx = j >> 5, o = j & 31;
        int ic = idx & 15, pos = idx >> 4;
        sm->w2s[j] = w2g[(o*16 + ic)*9 + pos];
    }
    for (int j = tid; j < 288*3; j += NTHREADS) {
        int idx = j / 3, o = j - idx*3;
        int pos = idx >> 5, ic = idx & 31;
        sm->w3s[j] = w3g[(o*32 + ic)*9 + pos];
    }

    // ---- per-lane weight registers ----
    const int c1 = lane & 15;            // layer-1 channel for this lane
    float w1r[9];
    #pragma unroll
    for (int k = 0; k < 9; k++) w1r[k] = w1g[c1*9 + k];
    const float b1r = b1g[c1];
    const float b2r = b2g[lane];         // layer-2 out channel == lane
    const float b30 = b3g[0], b31 = b3g[1], b32 = b3g[2];

    __syncthreads();

    const float* ximg = xg + (size_t)img * (T_STEPS*128*128);

    for (int t = 0; t < T_STEPS; t++) {
        // ---- stage x tile (zero-padded SAME) ----
        const float* xt = ximg + (size_t)t * (128*128);
        for (int i = tid; i < XH*XW; i += NTHREADS) {
            int ry = i / XW, rx = i - ry*XW;
            int gy = y0 + ry - 3, gx = x0 + rx - 3;
            float v = 0.f;
            if ((unsigned)gy < 128u && (unsigned)gx < 128u) v = __ldg(&xt[gy*128 + gx]);
            sm->xs[i] = v;
        }
        __syncthreads();

        // ---- layer 1: half-warp = 16 channels of one pixel ----
        {
            const int half = lane >> 4;
            for (int base = warp; base < N1/2; base += NWARPS) {
                const int p  = base*2 + half;
                const int ry = p / R1W, rx = p - ry*R1W;
                float a = b1r;
                #pragma unroll
                for (int k = 0; k < 9; k++)
                    a = fmaf(w1r[k], sm->xs[(ry + k/3)*XW + (rx + k - (k/3)*3)], a);
                float v = (sm->v1[p*16 + c1] + a) * 0.5f;   // v += (x-v)/2
                const int gy = y0 + ry - 2, gx = x0 + rx - 2;
                const bool sp = (v >= 1.0f) && ((unsigned)gy < 128u) && ((unsigned)gx < 128u);
                sm->v1[p*16 + c1] = sp ? 0.f : v;           // hard reset
                unsigned bal = __ballot_sync(0xffffffffu, sp);
                if (c1 == 0) sm->s1m[p] = (bal >> (half << 4)) & 0xffffu;
            }
        }
        __syncthreads();

        // ---- layer 2: warp = 32 out channels of one pixel ----
        for (int p = warp; p < N2; p += NWARPS) {
            const int ry = p / R2W, rx = p - ry*R2W;

            unsigned m[9];
            #pragma unroll
            for (int ky = 0; ky < 3; ky++)
                #pragma unroll
                for (int kx = 0; kx < 3; kx++)
                    m[ky*3+kx] = sm->s1m[(ry+ky)*R2W + rx+kx + ky*(R1W-R2W) /*dummy*/];
            // fix addressing explicitly (R1W row stride):
            #pragma unroll
            for (int ky = 0; ky < 3; ky++)
                #pragma unroll
                for (int kx = 0; kx < 3; kx++)
                    m[ky*3+kx] = sm->s1m[(ry+ky)*R1W + rx+kx];

            unsigned long long a0 = (unsigned long long)m[0] | ((unsigned long long)m[1]<<16)
                                  | ((unsigned long long)m[2]<<32) | ((unsigned long long)m[3]<<48);
            unsigned long long a1 = (unsigned long long)m[4] | ((unsigned long long)m[5]<<16)
                                  | ((unsigned long long)m[6]<<32) | ((unsigned long long)m[7]<<48);
            unsigned long long a2 = (unsigned long long)m[8];

            float acc = b2r;
            while (a0) { int b = __ffsll((long long)a0) - 1; a0 &= a0 - 1; acc += sm->w2s[(b<<5) + lane]; }
            while (a1) { int b = __ffsll((long long)a1) - 1; a1 &= a1 - 1; acc += sm->w2s[((64+b)<<5) + lane]; }
            while (a2) { int b = __ffsll((long long)a2) - 1; a2 &= a2 - 1; acc += sm->w2s[((128+b)<<5) + lane]; }

            float v = (sm->v2[p*32 + lane] + acc) * 0.5f;
            const int gy = y0 + ry - 1, gx = x0 + rx - 1;
            const bool sp = (v >= 1.0f) && ((unsigned)gy < 128u) && ((unsigned)gx < 128u);
            sm->v2[p*32 + lane] = sp ? 0.f : v;
            unsigned bal = __ballot_sync(0xffffffffu, sp);
            if (lane == 0) sm->s2m[p] = bal;
        }
        __syncthreads();

        // ---- layer 3: 2 threads per pixel (1024 thr, 512 px) ----
        {
            const int pix  = tid >> 1;           // 0..511
            const int half = tid & 1;            // mask split: 0 -> m0..m3, 1 -> m4..m8
            const int ry = pix >> 5, rx = pix & 31;

            float A0, A1, A2;
            if (half == 0) { A0 = b30; A1 = b31; A2 = b32; }
            else           { A0 = 0.f; A1 = 0.f; A2 = 0.f; }

            const int mi0 = half * 4;            // first mask index (0 or 4)
            const int nm  = 4 + half;            // 4 or 5 masks
            for (int k = 0; k < nm; k++) {
                const int mi = mi0 + k;
                const int ky = mi / 3, kx = mi - ky*3;
                unsigned mm = sm->s2m[(ry+ky)*R2W + rx+kx];
                const int base = mi << 5;        // channel base = mi*32
                while (mm) {
                    int b = __ffs(mm) - 1; mm &= mm - 1;
                    const float* wp = &sm->w3s[(base + b)*3];
                    A0 += wp[0]; A1 += wp[1]; A2 += wp[2];
                }
            }
            // combine the two halves (adjacent lanes)
            A0 += __shfl_xor_sync(0xffffffffu, A0, 1);
            A1 += __shfl_xor_sync(0xffffffffu, A1, 1);
            A2 += __shfl_xor_sync(0xffffffffu, A2, 1);

            if (half == 0) {
                float av[3] = {A0, A1, A2};
                #pragma unroll
                for (int k = 0; k < 3; k++) {
                    float v = (sm->v3[k*N3 + pix] + av[k]) * 0.5f;
                    bool sp = v >= 1.0f;
                    sm->v3[k*N3 + pix] = sp ? 0.f : v;
                    if (sp) sm->accv[k*N3 + pix] += 1.0f;
                }
            }
        }
        __syncthreads();
    }

    // ---- output: sigmoid(acc / T) ----
    if (tid < N3) {
        const int p  = tid;
        const int gy = y0 + (p >> 5), gx = x0 + (p & 31);
        #pragma unroll
        for (int k = 0; k < 3; k++) {
            float a = sm->accv[k*N3 + p] * (1.0f / T_STEPS);
            outg[((size_t)(img*3 + k)*128 + gy)*128 + gx] = 1.0f / (1.0f + expf(-a));
        }
    }
}

extern "C" void kernel_launch(void* const* d_in, const int* in_sizes, int n_in,
                              void* d_out, int out_size)
{
    (void)in_sizes; (void)n_in; (void)out_size;
    const float* x  = (const float*)d_in[0];
    const float* w1 = (const float*)d_in[1];
    const float* b1 = (const float*)d_in[2];
    const float* w2 = (const float*)d_in[3];
    const float* b2 = (const float*)d_in[4];
    const float* w3 = (const float*)d_in[5];
    const float* b3 = (const float*)d_in[6];
    float* out = (float*)d_out;

    cudaFuncSetAttribute(snn_kernel, cudaFuncAttributeMaxDynamicSharedMemorySize,
                         (int)sizeof(SmemLayout));
    snn_kernel<<<256, NTHREADS, sizeof(SmemLayout)>>>(x, w1, b1, w2, b2, w3, b3, out);
}

// round 3
// speedup vs baseline: 1.0387x; 1.0173x over previous
#include <cuda_runtime.h>
#include <math.h>

// CoarseSNN: 3-layer spiking CNN, T=200 steps, B=8, H=W=128.
// Persistent kernel, 256 independent CTAs, each owns a 16x32 interior tile with
// redundant halo LIF state in SMEM (no inter-CTA traffic ever). Spikes are
// bitmasks; conv2/conv3 iterate set bits only.
// R3: cut warp-issued instructions (we are issue-bound):
//  - data-parallel pack pass builds 48-bit row-triple masks once, removing the
//    warp-uniform 9xLDS+pack from every layer-2 pixel (was paid 32x per warp)
//  - precomputed validity bytes replace per-step boundary ALU
//  - layer-3 weights padded to float4 (LDS.128 per spike), masks iterated raw
//  - x[t+1] register prefetch hides LDG latency behind the whole step

#define T_STEPS  200
#define NTHREADS 1024
#define NWARPS   32

#define IH 16
#define IW 32
#define R2H 18
#define R2W 34
#define R1H 20
#define R1W 36
#define XH 22
#define XW 38

#define N1 (R1H*R1W)     // 720
#define N2 (R2H*R2W)     // 612
#define N3 (IH*IW)       // 512

struct SmemLayout {
    unsigned long long row64[N1 + 2]; // packed s1 row triples      5776 B
    float xs[XH*XW];                  //                            3344 B
    float v1[N1*16];                  //                           46080 B
    float v2[N2*32];                  //                           78336 B
    float v3[3*N3];                   //                            6144 B
    float accv[3*N3];                 //                            6144 B
    float w2s[144*32];                // [pos*16+ic][o]            18432 B
    float w3s4[288*4];                // [pos*32+ic][o pad4]        4608 B
    unsigned s1m[N1 + 2];             // 16-bit masks (+pad)        2888 B
    unsigned s2m[N2];                 // 32-bit masks               2448 B
    unsigned char valid1[N1];         //                             720 B
    unsigned char valid2[N2];         //                             612 B
};                                    // ~175.5 KB

__global__ void __launch_bounds__(NTHREADS, 1)
snn_kernel(const float* __restrict__ xg,  const float* __restrict__ w1g,
           const float* __restrict__ b1g, const float* __restrict__ w2g,
           const float* __restrict__ b2g, const float* __restrict__ w3g,
           const float* __restrict__ b3g, float* __restrict__ outg)
{
    extern __shared__ unsigned char smem_raw[];
    SmemLayout* sm = reinterpret_cast<SmemLayout*>(smem_raw);

    const int tid  = threadIdx.x;
    const int lane = tid & 31;
    const int warp = tid >> 5;

    const int bid  = blockIdx.x;
    const int img  = bid >> 5;          // 8 images
    const int tile = bid & 31;          // 32 tiles (8 rows x 4 cols)
    const int y0   = (tile >> 2) * IH;
    const int x0   = (tile & 3)  * IW;

    // ---- init state ----
    for (int i = tid; i < N1*16; i += NTHREADS) sm->v1[i] = 0.f;
    for (int i = tid; i < N2*32; i += NTHREADS) sm->v2[i] = 0.f;
    for (int i = tid; i < 3*N3;  i += NTHREADS) { sm->v3[i] = 0.f; sm->accv[i] = 0.f; }
    for (int i = tid; i < N1+2;  i += NTHREADS) sm->s1m[i] = 0u;

    // ---- stage weights ----
    for (int j = tid; j < 144*32; j += NTHREADS) {
        int idx = j >> 5, o = j & 31;
        int ic = idx & 15, pos = idx >> 4;
        sm->w2s[j] = w2g[(o*16 + ic)*9 + pos];
    }
    for (int j = tid; j < 288*4; j += NTHREADS) {
        int idx = j >> 2, k = j & 3;
        int pos = idx >> 5, ic = idx & 31;
        sm->w3s4[j] = (k < 3) ? w3g[(k*32 + ic)*9 + pos] : 0.f;
    }

    // ---- precompute validity bytes (once) ----
    for (int i = tid; i < N1; i += NTHREADS) {
        int ry = i / R1W, rx = i - ry*R1W;
        int gy = y0 + ry - 2, gx = x0 + rx - 2;
        sm->valid1[i] = ((unsigned)gy < 128u && (unsigned)gx < 128u) ? 1 : 0;
    }
    for (int i = tid; i < N2; i += NTHREADS) {
        int ry = i / R2W, rx = i - ry*R2W;
        int gy = y0 + ry - 1, gx = x0 + rx - 1;
        sm->valid2[i] = ((unsigned)gy < 128u && (unsigned)gx < 128u) ? 1 : 0;
    }

    // ---- per-lane weight registers ----
    const int c1 = lane & 15;
    float w1r[9];
    #pragma unroll
    for (int k = 0; k < 9; k++) w1r[k] = w1g[c1*9 + k];
    const float b1r = b1g[c1];
    const float b2r = b2g[lane];
    const float b30 = b3g[0], b31 = b3g[1], b32 = b3g[2];

    // ---- x prefetch setup: one element per thread, register-staged ----
    const float* ximg = xg + (size_t)img * (T_STEPS*128*128);
    const float* xptr = 0;
    float xreg = 0.f;
    if (tid < XH*XW) {
        int ry = tid / XW, rx = tid - ry*XW;
        int gy = y0 + ry - 3, gx = x0 + rx - 3;
        if ((unsigned)gy < 128u && (unsigned)gx < 128u) {
            xptr = ximg + gy*128 + gx;
            xreg = __ldg(xptr);
        }
    }

    __syncthreads();

    for (int t = 0; t < T_STEPS; t++) {
        // ---- stage x tile, then immediately prefetch next step's value ----
        if (tid < XH*XW) sm->xs[tid] = xreg;
        __syncthreads();
        if (xptr && (t+1) < T_STEPS) xreg = __ldg(xptr + (size_t)(t+1)*(128*128));

        // ---- layer 1: half-warp = 16 channels of one pixel ----
        {
            const int half = lane >> 4;
            for (int base = warp; base < N1/2; base += NWARPS) {
                const int p  = base*2 + half;
                const int ry = p / R1W, rx = p - ry*R1W;
                float a = b1r;
                #pragma unroll
                for (int k = 0; k < 9; k++)
                    a = fmaf(w1r[k], sm->xs[(ry + k/3)*XW + (rx + k - (k/3)*3)], a);
                float v = (sm->v1[p*16 + c1] + a) * 0.5f;
                const bool sp = (v >= 1.0f) && (sm->valid1[p] != 0);
                sm->v1[p*16 + c1] = sp ? 0.f : v;
                unsigned bal = __ballot_sync(0xffffffffu, sp);
                if (c1 == 0) sm->s1m[p] = (bal >> (half << 4)) & 0xffffu;
            }
        }
        __syncthreads();

        // ---- pack pass: 48-bit row-triple masks (data-parallel, ~free) ----
        if (tid < N1) {
            unsigned a = sm->s1m[tid], b = sm->s1m[tid+1], c = sm->s1m[tid+2];
            sm->row64[tid] = (unsigned long long)a
                           | ((unsigned long long)b << 16)
                           | ((unsigned long long)c << 32);
        }
        __syncthreads();

        // ---- layer 2: warp = 32 out channels of one pixel ----
        {
            int ry = 0, rx = warp;                 // warp < 32 < R2W
            for (int p = warp; p < N2; p += NWARPS) {
                float acc = b2r;
                const float* wl = sm->w2s + lane;
                #pragma unroll
                for (int ky = 0; ky < 3; ky++) {
                    unsigned long long w = sm->row64[(ry+ky)*R1W + rx];
                    unsigned lo = (unsigned)w;
                    unsigned hi = (unsigned)(w >> 32);
                    const float* wb = wl + ky*(48*32);
                    while (lo) {                     // bits: kx0/kx1 channels
                        int b = 31 - __clz(lo); lo ^= (1u << b);
                        acc += wb[b << 5];
                    }
                    const float* wb2 = wb + 32*32;
                    while (hi) {                     // bits: kx2 channels
                        int b = 31 - __clz(hi); hi ^= (1u << b);
                        acc += wb2[b << 5];
                    }
                }
                float v = (sm->v2[p*32 + lane] + acc) * 0.5f;
                const bool sp = (v >= 1.0f) && (sm->valid2[p] != 0);
                sm->v2[p*32 + lane] = sp ? 0.f : v;
                unsigned bal = __ballot_sync(0xffffffffu, sp);
                if (lane == 0) sm->s2m[p] = bal;
                rx += NWARPS;
                if (rx >= R2W) { rx -= R2W; ry++; }
            }
        }
        __syncthreads();

        // ---- layer 3: 2 threads per pixel, float4 weights ----
        {
            const int pix  = tid >> 1;
            const int half = tid & 1;
            const int ry = pix >> 5, rx = pix & 31;

            float A0, A1, A2;
            if (half == 0) { A0 = b30; A1 = b31; A2 = b32; }
            else           { A0 = 0.f; A1 = 0.f; A2 = 0.f; }

            const int mi0 = half * 4;
            const int miE = mi0 + 4 + half;        // 4 or 5 masks
            const float4* wv = reinterpret_cast<const float4*>(sm->w3s4);
            for (int mi = mi0; mi < miE; mi++) {
                const int ky = mi / 3, kx = mi - ky*3;
                unsigned mm = sm->s2m[(ry+ky)*R2W + rx+kx];
                const float4* wm = wv + (mi << 5);
                while (mm) {
                    int b = 31 - __clz(mm); mm ^= (1u << b);
                    float4 ww = wm[b];
                    A0 += ww.x; A1 += ww.y; A2 += ww.z;
                }
            }
            A0 += __shfl_xor_sync(0xffffffffu, A0, 1);
            A1 += __shfl_xor_sync(0xffffffffu, A1, 1);
            A2 += __shfl_xor_sync(0xffffffffu, A2, 1);

            if (half == 0) {
                float av[3] = {A0, A1, A2};
                #pragma unroll
                for (int k = 0; k < 3; k++) {
                    float v = (sm->v3[k*N3 + pix] + av[k]) * 0.5f;
                    bool sp = v >= 1.0f;
                    sm->v3[k*N3 + pix] = sp ? 0.f : v;
                    if (sp) sm->accv[k*N3 + pix] += 1.0f;
                }
            }
        }
        __syncthreads();
    }

    // ---- output: sigmoid(acc / T) ----
    if (tid < N3) {
        const int p  = tid;
        const int gy = y0 + (p >> 5), gx = x0 + (p & 31);
        #pragma unroll
        for (int k = 0; k < 3; k++) {
            float a = sm->accv[k*N3 + p] * (1.0f / T_STEPS);
            outg[((size_t)(img*3 + k)*128 + gy)*128 + gx] = 1.0f / (1.0f + expf(-a));
        }
    }
}

extern "C" void kernel_launch(void* const* d_in, const int* in_sizes, int n_in,
                              void* d_out, int out_size)
{
    (void)in_sizes; (void)n_in; (void)out_size;
    const float* x  = (const float*)d_in[0];
    const float* w1 = (const float*)d_in[1];
    const float* b1 = (const float*)d_in[2];
    const float* w2 = (const float*)d_in[3];
    const float* b2 = (const float*)d_in[4];
    const float* w3 = (const float*)d_in[5];
    const float* b3 = (const float*)d_in[6];
    float* out = (float*)d_out;

    cudaFuncSetAttribute(snn_kernel, cudaFuncAttributeMaxDynamicSharedMemorySize,
                         (int)sizeof(SmemLayout));
    snn_kernel<<<256, NTHREADS, sizeof(SmemLayout)>>>(x, w1, b1, w2, b2, w3, b3, out);
}